// round 3
// baseline (speedup 1.0000x reference)
#include <cuda_runtime.h>
#include <math.h>
#include <stdint.h>

#define TPB1 128
#define TPB2 1024

// ---------------------------------------------------------------------------
// leaf_mask dtype is ambiguous (jax bool). Detect at runtime from byte pattern:
//   int32 0/1   -> every 32-bit word is 0 or 1
//   float32 0/1 -> every 32-bit word is 0 or 0x3F800000
//   uint8 bool  -> otherwise (random 0/1 bytes)
// Misdetection probability with ~random masks is astronomically small; the
// all-zeros mask is consistent under every interpretation.
// ---------------------------------------------------------------------------
__device__ __forceinline__ int detect_mask_mode(const void* m) {
    const unsigned int* w = (const unsigned int*)m;
    int allBin = 1, allFloat = 1;
    for (int i = 0; i < 256; i++) {
        unsigned int v = w[i];
        if (v > 1u) allBin = 0;
        if (v != 0u && v != 0x3F800000u) allFloat = 0;
    }
    if (allBin) return 1;
    if (allFloat) return 2;
    return 0;
}

__device__ __forceinline__ float read_mask(const void* m, size_t i, int mode) {
    if (mode == 1) return ((const int*)m)[i] ? 1.0f : 0.0f;
    if (mode == 2) return (((const float*)m)[i] != 0.0f) ? 1.0f : 0.0f;
    return ((const unsigned char*)m)[i] ? 1.0f : 0.0f;
}

// ---------------------------------------------------------------------------
// Kernel 1: fused MLP -> masked sigmoid score per point.
//   x = [features(64), xyz(3)]  (67 dims; the reference provably drops the
//   variance feature), h1 = relu(x W1^T + b1), h2 = relu(h1 W2^T + b2),
//   s = sigmoid(h2 W3^T + b3);  bp = s * mask.
//
// Shared layout (dynamic):
//   sW1T[67*64]  transposed W1 (float4 broadcast loads, 256B-aligned rows)
//   sW2T[64*32]  transposed W2
//   sB1[64] sB2[32] sW3[32]
//   sRow[128*69] per-thread private input row (stride 69 -> conflict-free);
//                h1 is written back into the same row so layer-2's dynamic
//                j-index reads shared, not spilled local memory.
// ---------------------------------------------------------------------------
__global__ void __launch_bounds__(TPB1) mlp_kernel(
    const float* __restrict__ points, const float* __restrict__ features,
    const void* __restrict__ mask,
    const float* __restrict__ W1, const float* __restrict__ b1,
    const float* __restrict__ W2, const float* __restrict__ b2,
    const float* __restrict__ W3, const float* __restrict__ b3,
    float* __restrict__ bp, int M)
{
    extern __shared__ float smem_dyn[];
    float* sW1T = smem_dyn;                 // 67*64 = 4288
    float* sW2T = sW1T + 67 * 64;           // 64*32 = 2048
    float* sB1  = sW2T + 64 * 32;           // 64
    float* sB2  = sB1 + 64;                 // 32
    float* sW3  = sB2 + 32;                 // 32
    float* sRows = sW3 + 32;                // 128*69

    __shared__ int   sMode;
    __shared__ float sb3v;

    int tid = threadIdx.x;
    if (tid == 0) { sMode = detect_mask_mode(mask); sb3v = b3[0]; }

    // Cooperative weight loads (coalesced reads, transposed stores)
    for (int idx = tid; idx < 64 * 67; idx += TPB1) {
        int j = idx / 67, k = idx % 67;
        sW1T[k * 64 + j] = W1[idx];
    }
    for (int idx = tid; idx < 32 * 64; idx += TPB1) {
        int i = idx >> 6, j = idx & 63;
        sW2T[j * 32 + i] = W2[idx];
    }
    if (tid < 64) sB1[tid] = b1[tid];
    if (tid < 32) { sB2[tid] = b2[tid]; sW3[tid] = W3[tid]; }

    int blockStart = blockIdx.x * TPB1;

    // Stage input rows: features (coalesced) + points, stride-69 pad
    for (int idx = tid; idx < TPB1 * 64; idx += TPB1) {
        int r = idx >> 6, c = idx & 63;
        int gp = blockStart + r;
        if (gp < M) sRows[r * 69 + c] = features[(size_t)gp * 64 + c];
    }
    for (int idx = tid; idx < TPB1 * 3; idx += TPB1) {
        int r = idx / 3, c = idx % 3;
        int gp = blockStart + r;
        if (gp < M) sRows[r * 69 + 64 + c] = points[(size_t)gp * 3 + c];
    }
    __syncthreads();

    int gp = blockStart + tid;
    if (gp >= M) return;

    float* sRow = sRows + tid * 69;

    // Layer 1: 67 -> 64 (k dynamic, j fully unrolled; h1 in registers)
    float h1[64];
    #pragma unroll
    for (int j = 0; j < 64; j++) h1[j] = sB1[j];
    for (int k = 0; k < 67; k++) {
        float xk = sRow[k];
        const float4* w4 = (const float4*)&sW1T[k * 64];
        #pragma unroll
        for (int q = 0; q < 16; q++) {
            float4 w = w4[q];
            h1[4 * q + 0] = fmaf(xk, w.x, h1[4 * q + 0]);
            h1[4 * q + 1] = fmaf(xk, w.y, h1[4 * q + 1]);
            h1[4 * q + 2] = fmaf(xk, w.z, h1[4 * q + 2]);
            h1[4 * q + 3] = fmaf(xk, w.w, h1[4 * q + 3]);
        }
    }
    // relu(h1) back into private row (x is dead)
    #pragma unroll
    for (int j = 0; j < 64; j++) sRow[j] = fmaxf(h1[j], 0.0f);

    // Layer 2: 64 -> 32
    float h2[32];
    #pragma unroll
    for (int i = 0; i < 32; i++) h2[i] = sB2[i];
    for (int j = 0; j < 64; j++) {
        float hj = sRow[j];
        const float4* w4 = (const float4*)&sW2T[j * 32];
        #pragma unroll
        for (int q = 0; q < 8; q++) {
            float4 w = w4[q];
            h2[4 * q + 0] = fmaf(hj, w.x, h2[4 * q + 0]);
            h2[4 * q + 1] = fmaf(hj, w.y, h2[4 * q + 1]);
            h2[4 * q + 2] = fmaf(hj, w.z, h2[4 * q + 2]);
            h2[4 * q + 3] = fmaf(hj, w.w, h2[4 * q + 3]);
        }
    }

    // Layer 3: 32 -> 1, sigmoid, mask
    float acc = sb3v;
    #pragma unroll
    for (int i = 0; i < 32; i++) acc = fmaf(fmaxf(h2[i], 0.0f), sW3[i], acc);
    float s = 1.0f / (1.0f + expf(-acc));
    float m = read_mask(mask, (size_t)gp, sMode);
    bp[gp] = s * m;
}

// ---------------------------------------------------------------------------
// Block-wide sum over 1024 threads (32 warps). Uniform call sites only.
// ---------------------------------------------------------------------------
__device__ __forceinline__ float block_reduce_sum(float v, float* scratch) {
    #pragma unroll
    for (int o = 16; o > 0; o >>= 1) v += __shfl_down_sync(0xFFFFFFFFu, v, o);
    int w = threadIdx.x >> 5, l = threadIdx.x & 31;
    if (l == 0) scratch[w] = v;
    __syncthreads();
    if (w == 0) {
        float x = scratch[l];
        #pragma unroll
        for (int o = 16; o > 0; o >>= 1) x += __shfl_down_sync(0xFFFFFFFFu, x, o);
        if (l == 0) scratch[0] = x;
    }
    __syncthreads();
    float r = scratch[0];
    __syncthreads();   // scratch reused by the next reduction
    return r;
}

// ---------------------------------------------------------------------------
// Kernel 2: one block per batch. Computes n_leaf, (optionally) zeros scores,
// masked two-pass variance (clarity), stable selection of score>0.7 via block
// prefix scan (replicates argsort-by-index semantics), consecutive-pair
// distance variance, and the final clipped confidence.
// ---------------------------------------------------------------------------
__global__ void __launch_bounds__(TPB2) stats_kernel(
    const float* __restrict__ points, const void* __restrict__ mask,
    float* __restrict__ bp, float* __restrict__ conf, int N)
{
    extern __shared__ unsigned char smraw[];
    float* sS  = (float*)smraw;               // N scores (later reused for d[])
    int*   sSel = (int*)(sS + N);             // N selected indices
    unsigned char* sMu = (unsigned char*)(sSel + N);  // N mask bytes
    float* sRed  = (float*)(sMu + N);         // 32
    int*   sIRed = (int*)(sRed + 32);         // 32
    __shared__ int sMode, sCnt;

    int tid = threadIdx.x;
    int b = blockIdx.x;
    size_t base = (size_t)b * N;

    if (tid == 0) sMode = detect_mask_mode(mask);
    __syncthreads();
    int mode = sMode;

    // Pass 1: load scores + mask, n_leaf and sum(scores)
    float ssum = 0.0f, nlf = 0.0f;
    for (int i = tid; i < N; i += TPB2) {
        float s = bp[base + i];
        float m = read_mask(mask, base + i, mode);
        sS[i] = s;
        sMu[i] = (unsigned char)m;
        ssum += s;
        nlf += m;
    }
    ssum = block_reduce_sum(ssum, sRed);
    nlf  = block_reduce_sum(nlf, sRed);

    if (nlf < 10.0f) {
        // reference zeros scores entirely; confidence is 0
        for (int i = tid; i < N; i += TPB2) bp[base + i] = 0.0f;
        if (tid == 0) conf[b] = 0.0f;
        return;
    }

    // clarity = unbiased masked variance of scores (two-pass)
    float mean = ssum / nlf;
    float vs = 0.0f;
    for (int i = tid; i < N; i += TPB2) {
        if (sMu[i]) { float d = sS[i] - mean; vs += d * d; }
    }
    vs = block_reduce_sum(vs, sRed);
    float clarity = vs / (nlf - 1.0f);

    // Stable selection (score > 0.7) via block prefix scan over contiguous chunks
    int per = N / TPB2;
    int j0 = tid * per;
    int c = 0;
    for (int u = 0; u < per; u++) c += (sS[j0 + u] > 0.7f) ? 1 : 0;

    int lane = tid & 31, warp = tid >> 5;
    int incl = c;
    #pragma unroll
    for (int o = 1; o < 32; o <<= 1) {
        int t = __shfl_up_sync(0xFFFFFFFFu, incl, o);
        if (lane >= o) incl += t;
    }
    if (lane == 31) sIRed[warp] = incl;
    __syncthreads();
    if (warp == 0) {
        int v = sIRed[lane];
        int iv = v;
        #pragma unroll
        for (int o = 1; o < 32; o <<= 1) {
            int t = __shfl_up_sync(0xFFFFFFFFu, iv, o);
            if (lane >= o) iv += t;
        }
        sIRed[lane] = iv - v;      // exclusive warp base
        if (lane == 31) sCnt = iv; // total count
    }
    __syncthreads();
    int cnt = sCnt;

    float cf = 0.0f;
    if (cnt > 5) {                  // uniform branch (cnt from shared)
        int r = sIRed[warp] + (incl - c);
        for (int u = 0; u < per; u++) {
            if (sS[j0 + u] > 0.7f) sSel[r++] = j0 + u;
        }
        __syncthreads();

        // Consecutive-selected-pair distances; two-pass variance.
        int P = cnt - 1;            // >= 5, so P-1 >= 4 (no clamp needed)
        const float* pb = points + base * 3;
        float dsum = 0.0f;
        for (int j = tid; j < P; j += TPB2) {
            int a = sSel[j], e = sSel[j + 1];
            float dx = pb[3 * e]     - pb[3 * a];
            float dy = pb[3 * e + 1] - pb[3 * a + 1];
            float dz = pb[3 * e + 2] - pb[3 * a + 2];
            float dj = sqrtf(dx * dx + dy * dy + dz * dz);
            sS[j] = dj;             // sS no longer needed as scores
            dsum += dj;
        }
        dsum = block_reduce_sum(dsum, sRed);  // barrier also orders sS writes
        float meanD = dsum / (float)P;
        float dv = 0.0f;
        for (int j = tid; j < P; j += TPB2) {
            float t = sS[j] - meanD;
            dv += t * t;
        }
        dv = block_reduce_sum(dv, sRed);
        float dvar = dv / (float)(P - 1);
        float cont = fminf(1.0f / (dvar + 1e-8f), 1.0f);
        cf = fminf(fmaxf(clarity * cont, 0.0f), 1.0f);
    }
    if (tid == 0) conf[b] = cf;
}

// ---------------------------------------------------------------------------
// Launch: memcpy(features passthrough) + mlp + per-batch stats, one stream,
// fully graph-capturable, no allocations.
// Output layout (float32): [boundary_prob B*N][features B*N*F][confidence B]
// ---------------------------------------------------------------------------
extern "C" void kernel_launch(void* const* d_in, const int* in_sizes, int n_in,
                              void* d_out, int out_size)
{
    const float* points   = (const float*)d_in[0];
    const float* features = (const float*)d_in[1];
    const void*  mask     = d_in[2];
    const float* W1 = (const float*)d_in[3];
    const float* b1 = (const float*)d_in[4];
    const float* W2 = (const float*)d_in[5];
    const float* b2 = (const float*)d_in[6];
    const float* W3 = (const float*)d_in[7];
    const float* b3 = (const float*)d_in[8];

    int M = in_sizes[2];                 // B*N total points
    int F = in_sizes[1] / M;             // 64
    long long Bll = (long long)out_size - (long long)M * (1 + F);
    int B = (Bll >= 1 && Bll <= M && (M % (int)Bll) == 0) ? (int)Bll : 4;
    int N = M / B;

    float* bp = (float*)d_out;
    float* featout = bp + M;
    float* conf = featout + (size_t)M * F;

    size_t smem1 = (size_t)(67 * 64 + 64 * 32 + 64 + 32 + 32) * sizeof(float)
                 + (size_t)TPB1 * 69 * sizeof(float);
    size_t smem2 = (size_t)N * sizeof(float)      // sS
                 + (size_t)N * sizeof(int)        // sSel
                 + (size_t)N                      // sMu
                 + 32 * sizeof(float) + 32 * sizeof(int);

    cudaFuncSetAttribute(mlp_kernel, cudaFuncAttributeMaxDynamicSharedMemorySize, (int)smem1);
    cudaFuncSetAttribute(stats_kernel, cudaFuncAttributeMaxDynamicSharedMemorySize, (int)smem2);

    // features pass-through
    cudaMemcpyAsync(featout, features, (size_t)M * F * sizeof(float),
                    cudaMemcpyDeviceToDevice);

    int grid1 = (M + TPB1 - 1) / TPB1;
    mlp_kernel<<<grid1, TPB1, smem1>>>(points, features, mask,
                                       W1, b1, W2, b2, W3, b3, bp, M);
    stats_kernel<<<B, TPB2, smem2>>>(points, mask, bp, conf, N);
}

// round 8
// speedup vs baseline: 1.3356x; 1.3356x over previous
#include <cuda_runtime.h>
#include <math.h>
#include <stdint.h>

#define TPB1 128
#define TPB2 1024

// ---------------------------------------------------------------------------
// leaf_mask dtype is ambiguous (jax bool). Detect at runtime from byte
// pattern, PARALLELIZED across the block (old version had thread 0 do 256
// serial L2 loads while everyone waited at the barrier — ~10us of pure
// latency per block):
//   int32 0/1   -> every 32-bit word is 0 or 1
//   float32 0/1 -> every word is 0 or 0x3F800000
//   uint8 bool  -> otherwise
// Each of the first `nw` threads checks one word; __syncthreads_and combines.
// Misdetection probability with random 0/1 masks: <= 8^-128. All-zero masks
// are consistent under every interpretation.
// ---------------------------------------------------------------------------
__device__ __forceinline__ int detect_mask_mode_par(const void* m, int tid, int nw) {
    int ok = 1, okf = 1;
    if (tid < nw) {
        unsigned int v = ((const unsigned int*)m)[tid];
        ok  = (v <= 1u);
        okf = (v == 0u || v == 0x3F800000u);
    }
    int allBin   = __syncthreads_and(ok);
    int allFloat = __syncthreads_and(okf);
    return allBin ? 1 : (allFloat ? 2 : 0);
}

__device__ __forceinline__ float read_mask(const void* m, size_t i, int mode) {
    if (mode == 1) return ((const int*)m)[i] ? 1.0f : 0.0f;
    if (mode == 2) return (((const float*)m)[i] != 0.0f) ? 1.0f : 0.0f;
    return ((const unsigned char*)m)[i] ? 1.0f : 0.0f;
}

// ---------------------------------------------------------------------------
// Kernel 1: fused MLP -> masked sigmoid score per point + features passthrough.
//   x = [features(64), xyz(3)], h1 = relu(x W1^T + b1),
//   h2 = relu(h1 W2^T + b2), s = sigmoid(h2 W3^T + b3), bp = s * mask.
//
// Shared (dynamic), ~35 KB/block -> 4 blocks/SM (reg-capped via launch_bounds):
//   sW1T[67*64]  transposed W1 (float4 broadcast rows)
//   sW2T[64*32]  transposed W2
//   sB1[64] sB2[32] sW3[32]
//   sX[128*17]   16-feature chunk per point, stride 17 (gcd(17,32)=1 ->
//                conflict-free per-thread row reads). Reused across 4 chunks.
// xyz is loaded straight from global (contiguous 12B/thread -> coalesced).
// Layer 2 is fully unrolled so h1 stays in registers (no shared round-trip).
// ---------------------------------------------------------------------------
__global__ void __launch_bounds__(TPB1, 4) mlp_kernel(
    const float* __restrict__ points, const float* __restrict__ features,
    const void* __restrict__ mask,
    const float* __restrict__ W1, const float* __restrict__ b1,
    const float* __restrict__ W2, const float* __restrict__ b2,
    const float* __restrict__ W3, const float* __restrict__ b3,
    float* __restrict__ bp, float* __restrict__ featout, int M)
{
    extern __shared__ float smem_dyn[];
    float* sW1T = smem_dyn;                 // 67*64 = 4288
    float* sW2T = sW1T + 67 * 64;           // 64*32 = 2048
    float* sB1  = sW2T + 64 * 32;           // 64
    float* sB2  = sB1 + 64;                 // 32
    float* sW3  = sB2 + 32;                 // 32
    float* sX   = sW3 + 32;                 // 128*17 = 2176

    __shared__ float sb3v;

    int tid = threadIdx.x;
    int blockStart = blockIdx.x * TPB1;
    int gp = blockStart + tid;

    // Parallel mask-mode detect (includes a block barrier)
    int mode = detect_mask_mode_par(mask, tid, TPB1);
    if (tid == 0) sb3v = b3[0];

    // Cooperative weight loads (coalesced reads, transposed stores)
    for (int idx = tid; idx < 64 * 67; idx += TPB1) {
        int j = idx / 67, k = idx % 67;
        sW1T[k * 64 + j] = W1[idx];
    }
    for (int idx = tid; idx < 32 * 64; idx += TPB1) {
        int i = idx >> 6, j = idx & 63;
        sW2T[j * 32 + i] = W2[idx];
    }
    if (tid < 64) sB1[tid] = b1[tid];
    if (tid < 32) { sB2[tid] = b2[tid]; sW3[tid] = W3[tid]; }

    // Fused features passthrough for this block's rows (float4, coalesced;
    // also warms L2 for the staging reads below). Hidden under FFMA.
    {
        int nrow = min(TPB1, M - blockStart);
        if (nrow > 0) {
            const float4* fin4 = (const float4*)features + (size_t)blockStart * 16;
            float4*       fo4  = (float4*)featout        + (size_t)blockStart * 16;
            int tot = nrow * 16;
            for (int i = tid; i < tot; i += TPB1) fo4[i] = fin4[i];
        }
    }

    // Layer 1 accumulators
    float h1[64];
    #pragma unroll
    for (int j = 0; j < 64; j++) h1[j] = sB1[j];

    // 4 chunks of 16 feature dims each, staged through sX
    for (int c = 0; c < 4; c++) {
        __syncthreads();   // compute(c-1) done before restaging (also orders
                           // weight stores before first compute)
        for (int idx = tid; idx < TPB1 * 16; idx += TPB1) {
            int r = idx >> 4, kk = idx & 15;
            int g = blockStart + r;
            sX[r * 17 + kk] = (g < M) ? features[(size_t)g * 64 + c * 16 + kk] : 0.0f;
        }
        __syncthreads();

        const float* xr = sX + tid * 17;
        #pragma unroll
        for (int kk = 0; kk < 16; kk++) {
            float xk = xr[kk];
            const float4* w4 = (const float4*)&sW1T[(c * 16 + kk) * 64];
            #pragma unroll
            for (int q = 0; q < 16; q++) {
                float4 w = w4[q];
                h1[4 * q + 0] = fmaf(xk, w.x, h1[4 * q + 0]);
                h1[4 * q + 1] = fmaf(xk, w.y, h1[4 * q + 1]);
                h1[4 * q + 2] = fmaf(xk, w.z, h1[4 * q + 2]);
                h1[4 * q + 3] = fmaf(xk, w.w, h1[4 * q + 3]);
            }
        }
    }

    // xyz tail (k = 64..66), straight from global (coalesced 12B/thread)
    {
        float p0 = 0.f, p1 = 0.f, p2 = 0.f;
        if (gp < M) {
            p0 = points[(size_t)gp * 3 + 0];
            p1 = points[(size_t)gp * 3 + 1];
            p2 = points[(size_t)gp * 3 + 2];
        }
        #pragma unroll
        for (int k = 0; k < 3; k++) {
            float xk = (k == 0) ? p0 : (k == 1) ? p1 : p2;
            const float4* w4 = (const float4*)&sW1T[(64 + k) * 64];
            #pragma unroll
            for (int q = 0; q < 16; q++) {
                float4 w = w4[q];
                h1[4 * q + 0] = fmaf(xk, w.x, h1[4 * q + 0]);
                h1[4 * q + 1] = fmaf(xk, w.y, h1[4 * q + 1]);
                h1[4 * q + 2] = fmaf(xk, w.z, h1[4 * q + 2]);
                h1[4 * q + 3] = fmaf(xk, w.w, h1[4 * q + 3]);
            }
        }
    }

    // Layer 2: 64 -> 32, fully unrolled so h1[j] stays a static register
    float h2[32];
    #pragma unroll
    for (int i = 0; i < 32; i++) h2[i] = sB2[i];
    #pragma unroll
    for (int j = 0; j < 64; j++) {
        float hj = fmaxf(h1[j], 0.0f);
        const float4* w4 = (const float4*)&sW2T[j * 32];
        #pragma unroll
        for (int q = 0; q < 8; q++) {
            float4 w = w4[q];
            h2[4 * q + 0] = fmaf(hj, w.x, h2[4 * q + 0]);
            h2[4 * q + 1] = fmaf(hj, w.y, h2[4 * q + 1]);
            h2[4 * q + 2] = fmaf(hj, w.z, h2[4 * q + 2]);
            h2[4 * q + 3] = fmaf(hj, w.w, h2[4 * q + 3]);
        }
    }

    // Layer 3: 32 -> 1, sigmoid, mask
    if (gp < M) {
        float acc = sb3v;
        #pragma unroll
        for (int i = 0; i < 32; i++) acc = fmaf(fmaxf(h2[i], 0.0f), sW3[i], acc);
        float s = 1.0f / (1.0f + expf(-acc));
        float m = read_mask(mask, (size_t)gp, mode);
        bp[gp] = s * m;
    }
}

// ---------------------------------------------------------------------------
// Block-wide sum over 1024 threads (32 warps). Uniform call sites only.
// ---------------------------------------------------------------------------
__device__ __forceinline__ float block_reduce_sum(float v, float* scratch) {
    #pragma unroll
    for (int o = 16; o > 0; o >>= 1) v += __shfl_down_sync(0xFFFFFFFFu, v, o);
    int w = threadIdx.x >> 5, l = threadIdx.x & 31;
    if (l == 0) scratch[w] = v;
    __syncthreads();
    if (w == 0) {
        float x = scratch[l];
        #pragma unroll
        for (int o = 16; o > 0; o >>= 1) x += __shfl_down_sync(0xFFFFFFFFu, x, o);
        if (l == 0) scratch[0] = x;
    }
    __syncthreads();
    float r = scratch[0];
    __syncthreads();   // scratch reused by the next reduction
    return r;
}

// ---------------------------------------------------------------------------
// Kernel 2: one block per batch. n_leaf, optional zeroing, masked two-pass
// variance (clarity), stable selection of score>0.7 via block prefix scan,
// consecutive-pair distance variance, final clipped confidence.
// ---------------------------------------------------------------------------
__global__ void __launch_bounds__(TPB2) stats_kernel(
    const float* __restrict__ points, const void* __restrict__ mask,
    float* __restrict__ bp, float* __restrict__ conf, int N)
{
    extern __shared__ unsigned char smraw[];
    float* sS  = (float*)smraw;               // N scores (later reused for d[])
    int*   sSel = (int*)(sS + N);             // N selected indices
    unsigned char* sMu = (unsigned char*)(sSel + N);  // N mask bytes
    float* sRed  = (float*)(sMu + N);         // 32
    int*   sIRed = (int*)(sRed + 32);         // 32
    __shared__ int sCnt;

    int tid = threadIdx.x;
    int b = blockIdx.x;
    size_t base = (size_t)b * N;

    // Parallel mask-mode detect (contains barriers)
    int mode = detect_mask_mode_par(mask, tid, 256);

    // Pass 1: load scores + mask, n_leaf and sum(scores)
    float ssum = 0.0f, nlf = 0.0f;
    for (int i = tid; i < N; i += TPB2) {
        float s = bp[base + i];
        float m = read_mask(mask, base + i, mode);
        sS[i] = s;
        sMu[i] = (unsigned char)m;
        ssum += s;
        nlf += m;
    }
    ssum = block_reduce_sum(ssum, sRed);
    nlf  = block_reduce_sum(nlf, sRed);

    if (nlf < 10.0f) {
        for (int i = tid; i < N; i += TPB2) bp[base + i] = 0.0f;
        if (tid == 0) conf[b] = 0.0f;
        return;
    }

    // clarity = unbiased masked variance of scores (two-pass)
    float mean = ssum / nlf;
    float vs = 0.0f;
    for (int i = tid; i < N; i += TPB2) {
        if (sMu[i]) { float d = sS[i] - mean; vs += d * d; }
    }
    vs = block_reduce_sum(vs, sRed);
    float clarity = vs / (nlf - 1.0f);

    // Stable selection (score > 0.7) via block prefix scan over contiguous chunks
    int per = (N + TPB2 - 1) / TPB2;
    int j0 = tid * per;
    int c = 0;
    for (int u = 0; u < per; u++) {
        int j = j0 + u;
        if (j < N && sS[j] > 0.7f) c++;
    }

    int lane = tid & 31, warp = tid >> 5;
    int incl = c;
    #pragma unroll
    for (int o = 1; o < 32; o <<= 1) {
        int t = __shfl_up_sync(0xFFFFFFFFu, incl, o);
        if (lane >= o) incl += t;
    }
    if (lane == 31) sIRed[warp] = incl;
    __syncthreads();
    if (warp == 0) {
        int v = sIRed[lane];
        int iv = v;
        #pragma unroll
        for (int o = 1; o < 32; o <<= 1) {
            int t = __shfl_up_sync(0xFFFFFFFFu, iv, o);
            if (lane >= o) iv += t;
        }
        sIRed[lane] = iv - v;      // exclusive warp base
        if (lane == 31) sCnt = iv; // total count
    }
    __syncthreads();
    int cnt = sCnt;

    float cf = 0.0f;
    if (cnt > 5) {                  // uniform branch (cnt from shared)
        int r = sIRed[warp] + (incl - c);
        for (int u = 0; u < per; u++) {
            int j = j0 + u;
            if (j < N && sS[j] > 0.7f) sSel[r++] = j;
        }
        __syncthreads();

        // Consecutive-selected-pair distances; two-pass variance.
        int P = cnt - 1;            // >= 5, so P-1 >= 4
        const float* pb = points + base * 3;
        float dsum = 0.0f;
        for (int j = tid; j < P; j += TPB2) {
            int a = sSel[j], e = sSel[j + 1];
            float dx = pb[3 * e]     - pb[3 * a];
            float dy = pb[3 * e + 1] - pb[3 * a + 1];
            float dz = pb[3 * e + 2] - pb[3 * a + 2];
            float dj = sqrtf(dx * dx + dy * dy + dz * dz);
            sS[j] = dj;             // sS no longer needed as scores
            dsum += dj;
        }
        dsum = block_reduce_sum(dsum, sRed);  // barrier also orders sS writes
        float meanD = dsum / (float)P;
        float dv = 0.0f;
        for (int j = tid; j < P; j += TPB2) {
            float t = sS[j] - meanD;
            dv += t * t;
        }
        dv = block_reduce_sum(dv, sRed);
        float dvar = dv / (float)(P - 1);
        float cont = fminf(1.0f / (dvar + 1e-8f), 1.0f);
        cf = fminf(fmaxf(clarity * cont, 0.0f), 1.0f);
    }
    if (tid == 0) conf[b] = cf;
}

// ---------------------------------------------------------------------------
// Launch: mlp (with fused features passthrough) + per-batch stats.
// Graph-capturable, allocation-free.
// Output layout (float32): [boundary_prob B*N][features B*N*F][confidence B]
// ---------------------------------------------------------------------------
extern "C" void kernel_launch(void* const* d_in, const int* in_sizes, int n_in,
                              void* d_out, int out_size)
{
    const float* points   = (const float*)d_in[0];
    const float* features = (const float*)d_in[1];
    const void*  mask     = d_in[2];
    const float* W1 = (const float*)d_in[3];
    const float* b1 = (const float*)d_in[4];
    const float* W2 = (const float*)d_in[5];
    const float* b2 = (const float*)d_in[6];
    const float* W3 = (const float*)d_in[7];
    const float* b3 = (const float*)d_in[8];

    int M = in_sizes[2];                 // B*N total points
    int F = in_sizes[1] / M;             // 64
    long long Bll = (long long)out_size - (long long)M * (1 + F);
    int B = (Bll >= 1 && Bll <= M && (M % (int)Bll) == 0) ? (int)Bll : 4;
    int N = M / B;

    float* bp = (float*)d_out;
    float* featout = bp + M;
    float* conf = featout + (size_t)M * F;

    size_t smem1 = (size_t)(67 * 64 + 64 * 32 + 64 + 32 + 32 + TPB1 * 17) * sizeof(float);
    size_t smem2 = (size_t)N * sizeof(float)      // sS
                 + (size_t)N * sizeof(int)        // sSel
                 + (size_t)N                      // sMu
                 + 32 * sizeof(float) + 32 * sizeof(int);

    cudaFuncSetAttribute(mlp_kernel, cudaFuncAttributeMaxDynamicSharedMemorySize, (int)smem1);
    cudaFuncSetAttribute(stats_kernel, cudaFuncAttributeMaxDynamicSharedMemorySize, (int)smem2);

    int grid1 = (M + TPB1 - 1) / TPB1;
    mlp_kernel<<<grid1, TPB1, smem1>>>(points, features, mask,
                                       W1, b1, W2, b2, W3, b3, bp, featout, M);
    stats_kernel<<<B, TPB2, smem2>>>(points, mask, bp, conf, N);
}

// round 10
// speedup vs baseline: 1.4130x; 1.0580x over previous
#include <cuda_runtime.h>
#include <math.h>
#include <stdint.h>

#define TPB1 128
#define TPB2 1024

// Per-MLP-block partial sums {sum(score), sum(mask)} for the stats kernel.
// Static device scratch (allowed); supports up to 65536 MLP blocks (M <= 8.4M).
__device__ float2 g_part[65536];

// ---------------------------------------------------------------------------
// Packed fp32x2 helpers (Blackwell FFMA2 — 2 IEEE fp32 FMAs per instruction,
// bit-exact vs scalar FFMA; ptxas only emits it via explicit PTX).
// ---------------------------------------------------------------------------
typedef unsigned long long ull;

__device__ __forceinline__ ull pack2(float lo, float hi) {
    ull r; asm("mov.b64 %0, {%1, %2};" : "=l"(r) : "f"(lo), "f"(hi)); return r;
}
__device__ __forceinline__ void unpack2(ull v, float& lo, float& hi) {
    asm("mov.b64 {%0, %1}, %2;" : "=f"(lo), "=f"(hi) : "l"(v));
}
__device__ __forceinline__ ull ffma2(ull a, ull b, ull c) {
    ull d; asm("fma.rn.f32x2 %0, %1, %2, %3;" : "=l"(d) : "l"(a), "l"(b), "l"(c));
    return d;
}

// ---------------------------------------------------------------------------
// leaf_mask dtype detect (parallelized; jax bool is dtype-ambiguous):
//   int32 0/1 -> 1, float32 0/1.0 -> 2, uint8 bool -> 0.
// ---------------------------------------------------------------------------
__device__ __forceinline__ int detect_mask_mode_par(const void* m, int tid, int nw) {
    int ok = 1, okf = 1;
    if (tid < nw) {
        unsigned int v = ((const unsigned int*)m)[tid];
        ok  = (v <= 1u);
        okf = (v == 0u || v == 0x3F800000u);
    }
    int allBin   = __syncthreads_and(ok);
    int allFloat = __syncthreads_and(okf);
    return allBin ? 1 : (allFloat ? 2 : 0);
}

__device__ __forceinline__ float read_mask(const void* m, size_t i, int mode) {
    if (mode == 1) return ((const int*)m)[i] ? 1.0f : 0.0f;
    if (mode == 2) return (((const float*)m)[i] != 0.0f) ? 1.0f : 0.0f;
    return ((const unsigned char*)m)[i] ? 1.0f : 0.0f;
}

// ---------------------------------------------------------------------------
// Kernel 1: fused MLP (FFMA2 packed fp32) + features passthrough + per-block
// partial sums for the stats kernel.
//   x = [features(64), xyz(3)], h1 = relu(x W1^T + b1),
//   h2 = relu(h1 W2^T + b2), s = sigmoid(h2 W3^T + b3), bp = s*mask.
// h1 is kept as 32 packed fp32x2 register pairs (output-dim pairing: weight
// pairs come straight out of the transposed shared rows as ulonglong2, the
// scalar x_k is splat-packed once per k).
// ---------------------------------------------------------------------------
__global__ void __launch_bounds__(TPB1, 2) mlp_kernel(
    const float* __restrict__ points, const float* __restrict__ features,
    const void* __restrict__ mask,
    const float* __restrict__ W1, const float* __restrict__ b1,
    const float* __restrict__ W2, const float* __restrict__ b2,
    const float* __restrict__ W3, const float* __restrict__ b3,
    float* __restrict__ bp, float* __restrict__ featout, int M)
{
    extern __shared__ float smem_dyn[];
    float* sW1T = smem_dyn;                 // 67*64 = 4288 (16B-aligned rows)
    float* sW2T = sW1T + 67 * 64;           // 64*32 = 2048
    float* sB1  = sW2T + 64 * 32;           // 64
    float* sB2  = sB1 + 64;                 // 32
    float* sW3  = sB2 + 32;                 // 32
    float* sX   = sW3 + 32;                 // 128*17 = 2176

    __shared__ float sb3v;
    __shared__ float2 sPart[TPB1 / 32];

    int tid = threadIdx.x;
    int blockStart = blockIdx.x * TPB1;
    int gp = blockStart + tid;

    int mode = detect_mask_mode_par(mask, tid, TPB1);   // has a barrier
    if (tid == 0) sb3v = b3[0];

    // Cooperative weight loads (coalesced reads, transposed stores)
    for (int idx = tid; idx < 64 * 67; idx += TPB1) {
        int j = idx / 67, k = idx % 67;
        sW1T[k * 64 + j] = W1[idx];
    }
    for (int idx = tid; idx < 32 * 64; idx += TPB1) {
        int i = idx >> 6, j = idx & 63;
        sW2T[j * 32 + i] = W2[idx];
    }
    if (tid < 64) sB1[tid] = b1[tid];
    if (tid < 32) { sB2[tid] = b2[tid]; sW3[tid] = W3[tid]; }

    // Fused features passthrough (float4, coalesced; hidden under FFMA)
    {
        int nrow = min(TPB1, M - blockStart);
        if (nrow > 0) {
            const float4* fin4 = (const float4*)features + (size_t)blockStart * 16;
            float4*       fo4  = (float4*)featout        + (size_t)blockStart * 16;
            int tot = nrow * 16;
            for (int i = tid; i < tot; i += TPB1) fo4[i] = fin4[i];
        }
    }

    // Layer 1 accumulators: 32 packed pairs (64 outputs)
    ull h1p[32];
    {
        const ulonglong2* bb = (const ulonglong2*)sB1;
        #pragma unroll
        for (int i = 0; i < 16; i++) {
            ulonglong2 t = bb[i];
            h1p[2 * i] = t.x; h1p[2 * i + 1] = t.y;
        }
    }

    // 4 chunks of 16 feature dims, staged through sX (stride 17 -> no conflicts)
    for (int c = 0; c < 4; c++) {
        __syncthreads();   // previous chunk consumed / weight stores ordered
        for (int idx = tid; idx < TPB1 * 16; idx += TPB1) {
            int r = idx >> 4, kk = idx & 15;
            int g = blockStart + r;
            sX[r * 17 + kk] = (g < M) ? features[(size_t)g * 64 + c * 16 + kk] : 0.0f;
        }
        __syncthreads();

        const float* xr = sX + tid * 17;
        #pragma unroll
        for (int kk = 0; kk < 16; kk++) {
            float xk = xr[kk];
            ull xk2 = pack2(xk, xk);
            const ulonglong2* w2 = (const ulonglong2*)&sW1T[(c * 16 + kk) * 64];
            #pragma unroll
            for (int q = 0; q < 16; q++) {
                ulonglong2 w = w2[q];
                h1p[2 * q]     = ffma2(xk2, w.x, h1p[2 * q]);
                h1p[2 * q + 1] = ffma2(xk2, w.y, h1p[2 * q + 1]);
            }
        }
    }

    // xyz tail (k = 64..66), straight from global (coalesced 12B/thread)
    {
        float p0 = 0.f, p1 = 0.f, p2 = 0.f;
        if (gp < M) {
            p0 = points[(size_t)gp * 3 + 0];
            p1 = points[(size_t)gp * 3 + 1];
            p2 = points[(size_t)gp * 3 + 2];
        }
        #pragma unroll
        for (int k = 0; k < 3; k++) {
            float xk = (k == 0) ? p0 : (k == 1) ? p1 : p2;
            ull xk2 = pack2(xk, xk);
            const ulonglong2* w2 = (const ulonglong2*)&sW1T[(64 + k) * 64];
            #pragma unroll
            for (int q = 0; q < 16; q++) {
                ulonglong2 w = w2[q];
                h1p[2 * q]     = ffma2(xk2, w.x, h1p[2 * q]);
                h1p[2 * q + 1] = ffma2(xk2, w.y, h1p[2 * q + 1]);
            }
        }
    }

    // relu(h1) -> scalars
    float h1s[64];
    #pragma unroll
    for (int i = 0; i < 32; i++) {
        float lo, hi; unpack2(h1p[i], lo, hi);
        h1s[2 * i]     = fmaxf(lo, 0.0f);
        h1s[2 * i + 1] = fmaxf(hi, 0.0f);
    }

    // Layer 2: 64 -> 32, packed over outputs (16 pairs)
    ull h2p[16];
    {
        const ulonglong2* bb = (const ulonglong2*)sB2;
        #pragma unroll
        for (int i = 0; i < 8; i++) {
            ulonglong2 t = bb[i];
            h2p[2 * i] = t.x; h2p[2 * i + 1] = t.y;
        }
    }
    #pragma unroll
    for (int j = 0; j < 64; j++) {
        ull hj2 = pack2(h1s[j], h1s[j]);
        const ulonglong2* w2 = (const ulonglong2*)&sW2T[j * 32];
        #pragma unroll
        for (int q = 0; q < 8; q++) {
            ulonglong2 w = w2[q];
            h2p[2 * q]     = ffma2(hj2, w.x, h2p[2 * q]);
            h2p[2 * q + 1] = ffma2(hj2, w.y, h2p[2 * q + 1]);
        }
    }

    // Layer 3: 32 -> 1, sigmoid, mask
    float acc = sb3v;
    #pragma unroll
    for (int i = 0; i < 16; i++) {
        float lo, hi; unpack2(h2p[i], lo, hi);
        acc = fmaf(fmaxf(lo, 0.0f), sW3[2 * i], acc);
        acc = fmaf(fmaxf(hi, 0.0f), sW3[2 * i + 1], acc);
    }
    float s = 1.0f / (1.0f + expf(-acc));
    float m = (gp < M) ? read_mask(mask, (size_t)gp, mode) : 0.0f;
    float val = (gp < M) ? s * m : 0.0f;
    if (gp < M) bp[gp] = val;

    // Per-block partial sums for stats: {sum(score), sum(mask)} (deterministic)
    {
        float a = val, c2 = m;
        #pragma unroll
        for (int o = 16; o > 0; o >>= 1) {
            a  += __shfl_down_sync(0xFFFFFFFFu, a, o);
            c2 += __shfl_down_sync(0xFFFFFFFFu, c2, o);
        }
        int w = tid >> 5, l = tid & 31;
        if (l == 0) sPart[w] = make_float2(a, c2);
        __syncthreads();
        if (tid == 0) {
            float sa = 0.f, sc = 0.f;
            #pragma unroll
            for (int ww = 0; ww < TPB1 / 32; ww++) { sa += sPart[ww].x; sc += sPart[ww].y; }
            g_part[blockIdx.x] = make_float2(sa, sc);
        }
    }
}

// ---------------------------------------------------------------------------
// Block-wide sum over 1024 threads (32 warps). Uniform call sites only.
// ---------------------------------------------------------------------------
__device__ __forceinline__ float block_reduce_sum(float v, float* scratch) {
    #pragma unroll
    for (int o = 16; o > 0; o >>= 1) v += __shfl_down_sync(0xFFFFFFFFu, v, o);
    int w = threadIdx.x >> 5, l = threadIdx.x & 31;
    if (l == 0) scratch[w] = v;
    __syncthreads();
    if (w == 0) {
        float x = scratch[l];
        #pragma unroll
        for (int o = 16; o > 0; o >>= 1) x += __shfl_down_sync(0xFFFFFFFFu, x, o);
        if (l == 0) scratch[0] = x;
    }
    __syncthreads();
    float r = scratch[0];
    __syncthreads();
    return r;
}

// ---------------------------------------------------------------------------
// Kernel 2: one block per batch. Mean/n_leaf come pre-reduced from g_part
// (bpb = MLP blocks per batch; 0 -> fallback full pass). Single fused pass:
// clarity variance (mean known -> no cancellation) + selection count; then
// scan, scatter (predicate re-read from L1), single-pass distance variance.
// ---------------------------------------------------------------------------
__global__ void __launch_bounds__(TPB2) stats_kernel(
    const float* __restrict__ points, const void* __restrict__ mask,
    float* __restrict__ bp, float* __restrict__ conf, int N, int bpb)
{
    extern __shared__ unsigned char smraw[];
    int* sSel = (int*)smraw;                  // N selected indices
    __shared__ float sRed[32];
    __shared__ int   sIRed[32];
    __shared__ int   sCnt;
    __shared__ float sVS;

    int tid = threadIdx.x;
    int b = blockIdx.x;
    size_t base = (size_t)b * N;

    int mode = detect_mask_mode_par(mask, tid, 256);   // has barriers

    // n_leaf and sum(scores): pre-reduced partials, or fallback full pass
    float ssum, nlf;
    {
        float a = 0.f, c2 = 0.f;
        if (bpb > 0) {
            for (int i = tid; i < bpb; i += TPB2) {
                float2 p = g_part[b * bpb + i];
                a += p.x; c2 += p.y;
            }
        } else {
            for (int i = tid; i < N; i += TPB2) {
                a  += bp[base + i];
                c2 += read_mask(mask, base + i, mode);
            }
        }
        ssum = block_reduce_sum(a, sRed);
        nlf  = block_reduce_sum(c2, sRed);
    }

    if (nlf < 10.0f) {
        for (int i = tid; i < N; i += TPB2) bp[base + i] = 0.0f;
        if (tid == 0) conf[b] = 0.0f;
        return;
    }
    float mean = ssum / nlf;

    // Fused pass over contiguous per-thread chunks: variance + selection count
    int per = (N + TPB2 - 1) / TPB2;
    int j0 = tid * per;
    float vs = 0.0f;
    int c = 0;
    for (int u = 0; u < per; u++) {
        int j = j0 + u;
        if (j < N) {
            float sc = bp[base + j];
            float m = read_mask(mask, base + j, mode);
            if (m != 0.0f) { float d = sc - mean; vs += d * d; }
            if (sc > 0.7f) c++;
        }
    }

    // Combined: prefix scan of c + reduction of vs (one barrier structure)
    int lane = tid & 31, warp = tid >> 5;
    int incl = c;
    #pragma unroll
    for (int o = 1; o < 32; o <<= 1) {
        int t = __shfl_up_sync(0xFFFFFFFFu, incl, o);
        if (lane >= o) incl += t;
    }
    float vw = vs;
    #pragma unroll
    for (int o = 16; o > 0; o >>= 1) vw += __shfl_down_sync(0xFFFFFFFFu, vw, o);
    if (lane == 31) sIRed[warp] = incl;
    if (lane == 0)  sRed[warp] = vw;
    __syncthreads();
    if (warp == 0) {
        int v = sIRed[lane];
        int iv = v;
        #pragma unroll
        for (int o = 1; o < 32; o <<= 1) {
            int t = __shfl_up_sync(0xFFFFFFFFu, iv, o);
            if (lane >= o) iv += t;
        }
        sIRed[lane] = iv - v;      // exclusive warp base
        if (lane == 31) sCnt = iv; // total count
        float x = sRed[lane];
        #pragma unroll
        for (int o = 16; o > 0; o >>= 1) x += __shfl_down_sync(0xFFFFFFFFu, x, o);
        if (lane == 0) sVS = x;
    }
    __syncthreads();
    int cnt = sCnt;
    float clarity = sVS / (nlf - 1.0f);

    float cf = 0.0f;
    if (cnt > 5) {                 // uniform branch (cnt from shared)
        // Stable compaction: re-read predicate (L1 hit), scatter indices
        int r = sIRed[warp] + (incl - c);
        for (int u = 0; u < per; u++) {
            int j = j0 + u;
            if (j < N && bp[base + j] > 0.7f) sSel[r++] = j;
        }
        __syncthreads();

        // Single-pass distance variance over consecutive selected pairs
        int P = cnt - 1;           // >= 5
        const float* pb = points + base * 3;
        float sd = 0.0f, sd2 = 0.0f;
        for (int j = tid; j < P; j += TPB2) {
            int a = sSel[j], e = sSel[j + 1];
            float dx = pb[3 * e]     - pb[3 * a];
            float dy = pb[3 * e + 1] - pb[3 * a + 1];
            float dz = pb[3 * e + 2] - pb[3 * a + 2];
            float dj = sqrtf(dx * dx + dy * dy + dz * dz);
            sd += dj; sd2 += dj * dj;
        }
        sd  = block_reduce_sum(sd, sRed);
        sd2 = block_reduce_sum(sd2, sRed);
        float meanD = sd / (float)P;
        float dvar = fmaxf((sd2 - sd * meanD) / (float)(P - 1), 0.0f);
        float cont = fminf(1.0f / (dvar + 1e-8f), 1.0f);
        cf = fminf(fmaxf(clarity * cont, 0.0f), 1.0f);
    }
    if (tid == 0) conf[b] = cf;
}

// ---------------------------------------------------------------------------
// Launch. Graph-capturable, allocation-free.
// Output layout (float32): [boundary_prob B*N][features B*N*F][confidence B]
// ---------------------------------------------------------------------------
extern "C" void kernel_launch(void* const* d_in, const int* in_sizes, int n_in,
                              void* d_out, int out_size)
{
    const float* points   = (const float*)d_in[0];
    const float* features = (const float*)d_in[1];
    const void*  mask     = d_in[2];
    const float* W1 = (const float*)d_in[3];
    const float* b1 = (const float*)d_in[4];
    const float* W2 = (const float*)d_in[5];
    const float* b2 = (const float*)d_in[6];
    const float* W3 = (const float*)d_in[7];
    const float* b3 = (const float*)d_in[8];

    int M = in_sizes[2];                 // B*N total points
    int F = in_sizes[1] / M;             // 64
    long long Bll = (long long)out_size - (long long)M * (1 + F);
    int B = (Bll >= 1 && Bll <= M && (M % (int)Bll) == 0) ? (int)Bll : 4;
    int N = M / B;

    float* bp = (float*)d_out;
    float* featout = bp + M;
    float* conf = featout + (size_t)M * F;

    size_t smem1 = (size_t)(67 * 64 + 64 * 32 + 64 + 32 + 32 + TPB1 * 17) * sizeof(float);
    size_t smem2 = (size_t)N * sizeof(int);

    cudaFuncSetAttribute(mlp_kernel, cudaFuncAttributeMaxDynamicSharedMemorySize, (int)smem1);
    cudaFuncSetAttribute(stats_kernel, cudaFuncAttributeMaxDynamicSharedMemorySize, (int)smem2);

    int grid1 = (M + TPB1 - 1) / TPB1;
    int bpb = (N % TPB1 == 0 && grid1 <= 65536) ? (N / TPB1) : 0;

    mlp_kernel<<<grid1, TPB1, smem1>>>(points, features, mask,
                                       W1, b1, W2, b2, W3, b3, bp, featout, M);
    stats_kernel<<<B, TPB2, smem2>>>(points, mask, bp, conf, N, bpb);
}